// round 2
// baseline (speedup 1.0000x reference)
#include <cuda_runtime.h>
#include <cuda_bf16.h>
#include <math.h>

// Problem constants
#define TT 128
#define BB 32
#define VV 10000
#define HH 1024
#define M1 (TT*BB)          // 4096
#define BH (BB*HH)          // 32768

// ---------------- scratch (device globals; no allocation allowed) ----------
__device__ float g_Xz[M1*HH];
__device__ float g_Xr[M1*HH];
__device__ float g_Xh[M1*HH];
__device__ float g_Hs[TT*BB*HH];
__device__ float g_Z[BH];
__device__ float g_G[BH];

// ---------------- generic tiled SGEMM: C = A(MxK) * B(KxN) + bias ---------
// Row-major. M % 128 == 0, K % 8 == 0 assumed. N guarded (N % 4 == 0).
#define BM 128
#define BN 128
#define BK 8

__global__ __launch_bounds__(256)
void sgemm_bias(const float* __restrict__ A, const float* __restrict__ Bm,
                const float* __restrict__ bias, float* __restrict__ C,
                int M, int N, int K)
{
    __shared__ float As[BK][BM];
    __shared__ float Bs[BK][BN];

    const int tid = threadIdx.x;
    const int m0 = blockIdx.y * BM;
    const int n0 = blockIdx.x * BN;

    // A loads: 256 threads * 1 float4 = 128x8 tile
    const int arow = tid >> 1;
    const int acol = (tid & 1) * 4;
    // B loads: 256 threads * 1 float4 = 8x128 tile
    const int brow = tid >> 5;
    const int bcol = (tid & 31) * 4;

    const float* Ag = A + (size_t)(m0 + arow) * K + acol;
    const float* Bg = Bm + (size_t)brow * N + n0 + bcol;
    const bool bok = (n0 + bcol) < N;

    const int tx = tid & 15;
    const int ty = tid >> 4;

    float acc[8][8];
#pragma unroll
    for (int i = 0; i < 8; ++i)
#pragma unroll
        for (int j = 0; j < 8; ++j) acc[i][j] = 0.f;

    for (int k0 = 0; k0 < K; k0 += BK) {
        float4 av = *(const float4*)Ag;
        Ag += BK;
        float4 bv = make_float4(0.f, 0.f, 0.f, 0.f);
        if (bok) bv = *(const float4*)Bg;
        Bg += (size_t)BK * N;

        As[acol + 0][arow] = av.x;
        As[acol + 1][arow] = av.y;
        As[acol + 2][arow] = av.z;
        As[acol + 3][arow] = av.w;
        *(float4*)&Bs[brow][bcol] = bv;
        __syncthreads();

#pragma unroll
        for (int kk = 0; kk < BK; ++kk) {
            float rm[8], rn[8];
            *(float4*)&rm[0] = *(float4*)&As[kk][ty * 8];
            *(float4*)&rm[4] = *(float4*)&As[kk][ty * 8 + 4];
            *(float4*)&rn[0] = *(float4*)&Bs[kk][tx * 8];
            *(float4*)&rn[4] = *(float4*)&Bs[kk][tx * 8 + 4];
#pragma unroll
            for (int i = 0; i < 8; ++i)
#pragma unroll
                for (int j = 0; j < 8; ++j)
                    acc[i][j] += rm[i] * rn[j];
        }
        __syncthreads();
    }

    // epilogue with bias, N guarded (N % 4 == 0 so float4 is all-in or all-out)
#pragma unroll
    for (int i = 0; i < 8; ++i) {
        int row = m0 + ty * 8 + i;
#pragma unroll
        for (int j4 = 0; j4 < 8; j4 += 4) {
            int col = n0 + tx * 8 + j4;
            if (col < N) {
                float4 bb = *(const float4*)&bias[col];
                float4 v;
                v.x = acc[i][j4 + 0] + bb.x;
                v.y = acc[i][j4 + 1] + bb.y;
                v.z = acc[i][j4 + 2] + bb.z;
                v.w = acc[i][j4 + 3] + bb.w;
                *(float4*)&C[(size_t)row * N + col] = v;
            }
        }
    }
}

// ---------------- recurrence phase 1: Z, G = R*Hprev ------------------------
// grid: H/8 = 128 blocks, 256 threads. Each thread -> one (b, h) output pair.
__global__ __launch_bounds__(256)
void gru_phase1(const float* __restrict__ Hprev,
                const float* __restrict__ Xz_t, const float* __restrict__ Xr_t,
                const float* __restrict__ Whz, const float* __restrict__ Whr,
                float* __restrict__ Zout, float* __restrict__ Gout)
{
    __shared__ float Hp[32][132];
    __shared__ float Wz[128][8];
    __shared__ float Wr[128][8];

    const int tid = threadIdx.x;
    const int n0 = blockIdx.x * 8;
    const int b = tid >> 3;
    const int nn = tid & 7;

    float accz = 0.f, accr = 0.f;

    for (int kc = 0; kc < HH; kc += 128) {
        __syncthreads();
        // Hprev chunk: 32 x 128 floats = 1024 float4, 4 per thread
#pragma unroll
        for (int i = 0; i < 4; ++i) {
            int s = tid + i * 256;
            int row = s >> 5, c4 = s & 31;
            float4 v = *(const float4*)&Hprev[row * HH + kc + c4 * 4];
            *(float4*)&Hp[row][c4 * 4] = v;
        }
        // W chunks: 128 x 8 each
        {
            int wrow = tid >> 1, wc = (tid & 1) * 4;
            *(float4*)&Wz[wrow][wc] = *(const float4*)&Whz[(size_t)(kc + wrow) * HH + n0 + wc];
            *(float4*)&Wr[wrow][wc] = *(const float4*)&Whr[(size_t)(kc + wrow) * HH + n0 + wc];
        }
        __syncthreads();
#pragma unroll 32
        for (int k = 0; k < 128; ++k) {
            float hp = Hp[b][k];
            accz += hp * Wz[k][nn];
            accr += hp * Wr[k][nn];
        }
    }

    const int idx = b * HH + n0 + nn;
    float z = 1.f / (1.f + __expf(-(Xz_t[idx] + accz)));
    float r = 1.f / (1.f + __expf(-(Xr_t[idx] + accr)));
    Zout[idx] = z;
    Gout[idx] = r * Hprev[idx];
}

// ---------------- recurrence phase 2: Hnew ---------------------------------
__global__ __launch_bounds__(256)
void gru_phase2(const float* __restrict__ Hprev, const float* __restrict__ G,
                const float* __restrict__ Xh_t, const float* __restrict__ Whh,
                const float* __restrict__ Z, float* __restrict__ Hout)
{
    __shared__ float Gp[32][132];
    __shared__ float Wh[128][8];

    const int tid = threadIdx.x;
    const int n0 = blockIdx.x * 8;
    const int b = tid >> 3;
    const int nn = tid & 7;

    float acc = 0.f;

    for (int kc = 0; kc < HH; kc += 128) {
        __syncthreads();
#pragma unroll
        for (int i = 0; i < 4; ++i) {
            int s = tid + i * 256;
            int row = s >> 5, c4 = s & 31;
            float4 v = *(const float4*)&G[row * HH + kc + c4 * 4];
            *(float4*)&Gp[row][c4 * 4] = v;
        }
        {
            int wrow = tid >> 1, wc = (tid & 1) * 4;
            *(float4*)&Wh[wrow][wc] = *(const float4*)&Whh[(size_t)(kc + wrow) * HH + n0 + wc];
        }
        __syncthreads();
#pragma unroll 32
        for (int k = 0; k < 128; ++k) {
            acc += Gp[b][k] * Wh[k][nn];
        }
    }

    const int idx = b * HH + n0 + nn;
    float ht = tanhf(Xh_t[idx] + acc);
    float z = Z[idx];
    Hout[idx] = z * Hprev[idx] + (1.f - z) * ht;
}

// ---------------- H_last copy ----------------------------------------------
__global__ void copy_hlast(const float* __restrict__ src, float* __restrict__ dst)
{
    int i = blockIdx.x * blockDim.x + threadIdx.x;
    if (i < BH) dst[i] = src[i];
}

// ---------------- launch ----------------------------------------------------
extern "C" void kernel_launch(void* const* d_in, const int* in_sizes, int n_in,
                              void* d_out, int out_size)
{
    const float* inputs = (const float*)d_in[0];
    const float* H0     = (const float*)d_in[1];
    const float* W_xz   = (const float*)d_in[2];
    const float* W_hz   = (const float*)d_in[3];
    const float* b_z    = (const float*)d_in[4];
    const float* W_xr   = (const float*)d_in[5];
    const float* W_hr   = (const float*)d_in[6];
    const float* b_r    = (const float*)d_in[7];
    const float* W_xh   = (const float*)d_in[8];
    const float* W_hh   = (const float*)d_in[9];
    const float* b_h    = (const float*)d_in[10];
    const float* W_hq   = (const float*)d_in[11];
    const float* b_q    = (const float*)d_in[12];

    float* out = (float*)d_out;

    float *Xz, *Xr, *Xh, *Hs, *Zb, *Gb;
    cudaGetSymbolAddress((void**)&Xz, g_Xz);
    cudaGetSymbolAddress((void**)&Xr, g_Xr);
    cudaGetSymbolAddress((void**)&Xh, g_Xh);
    cudaGetSymbolAddress((void**)&Hs, g_Hs);
    cudaGetSymbolAddress((void**)&Zb, g_Z);
    cudaGetSymbolAddress((void**)&Gb, g_G);

    // 1) input projections: [4096,10000] @ [10000,1024] + bias  (x3)
    {
        dim3 grid(HH / BN, M1 / BM);
        sgemm_bias<<<grid, 256>>>(inputs, W_xz, b_z, Xz, M1, HH, VV);
        sgemm_bias<<<grid, 256>>>(inputs, W_xr, b_r, Xr, M1, HH, VV);
        sgemm_bias<<<grid, 256>>>(inputs, W_xh, b_h, Xh, M1, HH, VV);
    }

    // 2) recurrence: 128 steps, 2 kernels each
    for (int t = 0; t < TT; ++t) {
        const float* Hprev = (t == 0) ? H0 : (Hs + (size_t)(t - 1) * BH);
        const float* Xz_t = Xz + (size_t)t * BH;
        const float* Xr_t = Xr + (size_t)t * BH;
        const float* Xh_t = Xh + (size_t)t * BH;
        gru_phase1<<<HH / 8, 256>>>(Hprev, Xz_t, Xr_t, W_hz, W_hr, Zb, Gb);
        gru_phase2<<<HH / 8, 256>>>(Hprev, Gb, Xh_t, W_hh, Zb, Hs + (size_t)t * BH);
    }

    // 3) output projection: [4096,1024] @ [1024,10000] + b_q -> d_out
    {
        dim3 grid((VV + BN - 1) / BN, M1 / BM);
        sgemm_bias<<<grid, 256>>>(Hs, W_hq, b_q, out, M1, VV, HH);
    }

    // 4) H_last appended after outputs if the output buffer includes it
    if (out_size >= M1 * VV + BH) {
        copy_hlast<<<BH / 256, 256>>>(Hs + (size_t)(TT - 1) * BH,
                                      out + (size_t)M1 * VV);
    }
}

// round 3
// speedup vs baseline: 1.0592x; 1.0592x over previous
#include <cuda_runtime.h>
#include <cuda_bf16.h>
#include <math.h>

// Problem constants
#define TT 128
#define BB 32
#define VV 10000
#define HH 1024
#define M1 (TT*BB)          // 4096
#define BH (BB*HH)          // 32768

// ---------------- scratch (device globals; no allocation allowed) ----------
__device__ float g_Xz[M1*HH];
__device__ float g_Xr[M1*HH];
__device__ float g_Xh[M1*HH];
__device__ float g_Hs[TT*BB*HH];
__device__ float g_Z[BH];
__device__ float g_G[BH];

// ---------------- generic tiled SGEMM: C = A(MxK) * B(KxN) + bias ---------
// Row-major. M % 128 == 0, K % 8 == 0 assumed. N guarded (N % 4 == 0).
#define BM 128
#define BN 128
#define BK 8

__global__ __launch_bounds__(256)
void sgemm_bias(const float* __restrict__ A, const float* __restrict__ Bm,
                const float* __restrict__ bias, float* __restrict__ C,
                int M, int N, int K)
{
    __shared__ float As[BK][BM];
    __shared__ float Bs[BK][BN];

    const int tid = threadIdx.x;
    const int m0 = blockIdx.y * BM;
    const int n0 = blockIdx.x * BN;

    const int arow = tid >> 1;
    const int acol = (tid & 1) * 4;
    const int brow = tid >> 5;
    const int bcol = (tid & 31) * 4;

    const float* Ag = A + (size_t)(m0 + arow) * K + acol;
    const float* Bg = Bm + (size_t)brow * N + n0 + bcol;
    const bool bok = (n0 + bcol) < N;

    const int tx = tid & 15;
    const int ty = tid >> 4;

    float acc[8][8];
#pragma unroll
    for (int i = 0; i < 8; ++i)
#pragma unroll
        for (int j = 0; j < 8; ++j) acc[i][j] = 0.f;

    for (int k0 = 0; k0 < K; k0 += BK) {
        float4 av = *(const float4*)Ag;
        Ag += BK;
        float4 bv = make_float4(0.f, 0.f, 0.f, 0.f);
        if (bok) bv = *(const float4*)Bg;
        Bg += (size_t)BK * N;

        As[acol + 0][arow] = av.x;
        As[acol + 1][arow] = av.y;
        As[acol + 2][arow] = av.z;
        As[acol + 3][arow] = av.w;
        *(float4*)&Bs[brow][bcol] = bv;
        __syncthreads();

#pragma unroll
        for (int kk = 0; kk < BK; ++kk) {
            float rm[8], rn[8];
            *(float4*)&rm[0] = *(float4*)&As[kk][ty * 8];
            *(float4*)&rm[4] = *(float4*)&As[kk][ty * 8 + 4];
            *(float4*)&rn[0] = *(float4*)&Bs[kk][tx * 8];
            *(float4*)&rn[4] = *(float4*)&Bs[kk][tx * 8 + 4];
#pragma unroll
            for (int i = 0; i < 8; ++i)
#pragma unroll
                for (int j = 0; j < 8; ++j)
                    acc[i][j] += rm[i] * rn[j];
        }
        __syncthreads();
    }

#pragma unroll
    for (int i = 0; i < 8; ++i) {
        int row = m0 + ty * 8 + i;
#pragma unroll
        for (int j4 = 0; j4 < 8; j4 += 4) {
            int col = n0 + tx * 8 + j4;
            if (col < N) {
                float4 bb = *(const float4*)&bias[col];
                float4 v;
                v.x = acc[i][j4 + 0] + bb.x;
                v.y = acc[i][j4 + 1] + bb.y;
                v.z = acc[i][j4 + 2] + bb.z;
                v.w = acc[i][j4 + 3] + bb.w;
                *(float4*)&C[(size_t)row * N + col] = v;
            }
        }
    }
}

// ============================================================================
// Recurrence kernels (rewritten): float4-vectorized, conflict-free smem,
// 128 blocks to cover the chip, deep FMA ILP via float4 accumulators.
// ============================================================================
#define KC 256
#define PADW 4   // pad rows by 4 floats: row stride 260 -> 16B-aligned, banks spread

__device__ __forceinline__ float sigf(float x) {
    return 1.f / (1.f + __expf(-x));
}

// gru_zr: blocks 0..63 compute Z cols [blk*16, +16); blocks 64..127 compute
// R (and G = R * Hprev) for cols [(blk-64)*16, +16).
__global__ __launch_bounds__(256)
void gru_zr(const float* __restrict__ Hprev,
            const float* __restrict__ Xz_t, const float* __restrict__ Xr_t,
            const float* __restrict__ Whz, const float* __restrict__ Whr,
            float* __restrict__ Z, float* __restrict__ G)
{
    __shared__ float Hp[32][KC + PADW];
    __shared__ float Wt[16][KC + PADW];

    const int tid = threadIdx.x;
    const bool isR = blockIdx.x >= 64;
    const int c0 = (blockIdx.x & 63) * 16;
    const float* __restrict__ W = isR ? Whr : Whz;

    const int b  = tid >> 3;   // 0..31
    const int nn = tid & 7;    // 0..7 ; thread owns cols c0+nn and c0+nn+8

    float4 a0 = make_float4(0.f, 0.f, 0.f, 0.f);
    float4 a1 = make_float4(0.f, 0.f, 0.f, 0.f);

    for (int kc = 0; kc < HH; kc += KC) {
        __syncthreads();
        // Hprev chunk: 32 x KC floats = 2048 float4 -> 8 per thread, coalesced
#pragma unroll
        for (int i = 0; i < 8; ++i) {
            int s = tid + i * 256;       // float4 index
            int row = s >> 6;            // KC/4 = 64 float4 per row
            int c4 = s & 63;
            *(float4*)&Hp[row][c4 * 4] =
                *(const float4*)&Hprev[row * HH + kc + c4 * 4];
        }
        // W tile transposed: Wt[col][k], 16 x KC floats -> 16 per thread
#pragma unroll
        for (int i = 0; i < 16; ++i) {
            int s = tid + i * 256;
            int kk = s >> 4;
            int cc = s & 15;
            Wt[cc][kk] = W[(size_t)(kc + kk) * HH + c0 + cc];
        }
        __syncthreads();

#pragma unroll 8
        for (int kk = 0; kk < KC; kk += 4) {
            float4 h  = *(const float4*)&Hp[b][kk];
            float4 w0 = *(const float4*)&Wt[nn][kk];
            float4 w1 = *(const float4*)&Wt[nn + 8][kk];
            a0.x += h.x * w0.x; a0.y += h.y * w0.y;
            a0.z += h.z * w0.z; a0.w += h.w * w0.w;
            a1.x += h.x * w1.x; a1.y += h.y * w1.y;
            a1.z += h.z * w1.z; a1.w += h.w * w1.w;
        }
    }

    float s0 = (a0.x + a0.y) + (a0.z + a0.w);
    float s1 = (a1.x + a1.y) + (a1.z + a1.w);
    const int i0 = b * HH + c0 + nn;
    const int i1 = i0 + 8;

    if (!isR) {
        Z[i0] = sigf(Xz_t[i0] + s0);
        Z[i1] = sigf(Xz_t[i1] + s1);
    } else {
        float r0 = sigf(Xr_t[i0] + s0);
        float r1 = sigf(Xr_t[i1] + s1);
        G[i0] = r0 * Hprev[i0];
        G[i1] = r1 * Hprev[i1];
    }
}

// gru_h: 128 blocks x 8 cols. Hnew = Z*Hprev + (1-Z)*tanh(Xh + G @ Whh)
__global__ __launch_bounds__(256)
void gru_h(const float* __restrict__ Hprev, const float* __restrict__ G,
           const float* __restrict__ Xh_t, const float* __restrict__ Whh,
           const float* __restrict__ Z, float* __restrict__ Hout)
{
    __shared__ float Gp[32][KC + PADW];
    __shared__ float Wt[8][KC + PADW];

    const int tid = threadIdx.x;
    const int c0 = blockIdx.x * 8;

    const int b  = tid >> 3;
    const int nn = tid & 7;

    float4 a0 = make_float4(0.f, 0.f, 0.f, 0.f);

    for (int kc = 0; kc < HH; kc += KC) {
        __syncthreads();
#pragma unroll
        for (int i = 0; i < 8; ++i) {
            int s = tid + i * 256;
            int row = s >> 6;
            int c4 = s & 63;
            *(float4*)&Gp[row][c4 * 4] =
                *(const float4*)&G[row * HH + kc + c4 * 4];
        }
        // Wt: 8 x KC floats = 2048 -> 8 per thread
#pragma unroll
        for (int i = 0; i < 8; ++i) {
            int s = tid + i * 256;
            int kk = s >> 3;
            int cc = s & 7;
            Wt[cc][kk] = Whh[(size_t)(kc + kk) * HH + c0 + cc];
        }
        __syncthreads();

#pragma unroll 8
        for (int kk = 0; kk < KC; kk += 4) {
            float4 g = *(const float4*)&Gp[b][kk];
            float4 w = *(const float4*)&Wt[nn][kk];
            a0.x += g.x * w.x; a0.y += g.y * w.y;
            a0.z += g.z * w.z; a0.w += g.w * w.w;
        }
    }

    float s0 = (a0.x + a0.y) + (a0.z + a0.w);
    const int i0 = b * HH + c0 + nn;
    float ht = tanhf(Xh_t[i0] + s0);
    float z = Z[i0];
    Hout[i0] = z * Hprev[i0] + (1.f - z) * ht;
}

// ---------------- H_last copy ----------------------------------------------
__global__ void copy_hlast(const float* __restrict__ src, float* __restrict__ dst)
{
    int i = blockIdx.x * blockDim.x + threadIdx.x;
    if (i < BH) dst[i] = src[i];
}

// ---------------- launch ----------------------------------------------------
extern "C" void kernel_launch(void* const* d_in, const int* in_sizes, int n_in,
                              void* d_out, int out_size)
{
    const float* inputs = (const float*)d_in[0];
    const float* H0     = (const float*)d_in[1];
    const float* W_xz   = (const float*)d_in[2];
    const float* W_hz   = (const float*)d_in[3];
    const float* b_z    = (const float*)d_in[4];
    const float* W_xr   = (const float*)d_in[5];
    const float* W_hr   = (const float*)d_in[6];
    const float* b_r    = (const float*)d_in[7];
    const float* W_xh   = (const float*)d_in[8];
    const float* W_hh   = (const float*)d_in[9];
    const float* b_h    = (const float*)d_in[10];
    const float* W_hq   = (const float*)d_in[11];
    const float* b_q    = (const float*)d_in[12];

    float* out = (float*)d_out;

    float *Xz, *Xr, *Xh, *Hs, *Zb, *Gb;
    cudaGetSymbolAddress((void**)&Xz, g_Xz);
    cudaGetSymbolAddress((void**)&Xr, g_Xr);
    cudaGetSymbolAddress((void**)&Xh, g_Xh);
    cudaGetSymbolAddress((void**)&Hs, g_Hs);
    cudaGetSymbolAddress((void**)&Zb, g_Z);
    cudaGetSymbolAddress((void**)&Gb, g_G);

    // 1) input projections: [4096,10000] @ [10000,1024] + bias  (x3)
    {
        dim3 grid(HH / BN, M1 / BM);
        sgemm_bias<<<grid, 256>>>(inputs, W_xz, b_z, Xz, M1, HH, VV);
        sgemm_bias<<<grid, 256>>>(inputs, W_xr, b_r, Xr, M1, HH, VV);
        sgemm_bias<<<grid, 256>>>(inputs, W_xh, b_h, Xh, M1, HH, VV);
    }

    // 2) recurrence: 128 steps, 2 kernels each
    for (int t = 0; t < TT; ++t) {
        const float* Hprev = (t == 0) ? H0 : (Hs + (size_t)(t - 1) * BH);
        const float* Xz_t = Xz + (size_t)t * BH;
        const float* Xr_t = Xr + (size_t)t * BH;
        const float* Xh_t = Xh + (size_t)t * BH;
        gru_zr<<<128, 256>>>(Hprev, Xz_t, Xr_t, W_hz, W_hr, Zb, Gb);
        gru_h<<<128, 256>>>(Hprev, Gb, Xh_t, W_hh, Zb, Hs + (size_t)t * BH);
    }

    // 3) output projection: [4096,1024] @ [1024,10000] + b_q -> d_out
    {
        dim3 grid((VV + BN - 1) / BN, M1 / BM);
        sgemm_bias<<<grid, 256>>>(Hs, W_hq, b_q, out, M1, VV, HH);
    }

    // 4) H_last appended after outputs if the output buffer includes it
    if (out_size >= M1 * VV + BH) {
        copy_hlast<<<BH / 256, 256>>>(Hs + (size_t)(TT - 1) * BH,
                                      out + (size_t)M1 * VV);
    }
}

// round 4
// speedup vs baseline: 2.1563x; 2.0358x over previous
#include <cuda_runtime.h>
#include <cuda_bf16.h>
#include <math.h>
#include <stdint.h>

// Problem constants
#define TT 128
#define BB 32
#define VV 10000
#define HH 1024
#define M1 (TT*BB)          // 4096
#define BH (BB*HH)          // 32768

// ---------------- scratch (device globals; no allocation allowed) ----------
__device__ float g_Xz[M1*HH];
__device__ float g_Xr[M1*HH];
__device__ float g_Xh[M1*HH];
__device__ float g_Hs[TT*BB*HH];
__device__ float g_Z[BH];
__device__ float g_G[BH];

// ============================================================================
// TF32 tensor-core GEMM: C = A(MxK) * B(KxN) + bias
// Row-major A and B. M % 128 == 0, K % 16 == 0. N guarded (N % 4 == 0).
// Block tile 128x128x16, 256 threads = 8 warps, warp tile 32x64.
// ============================================================================
#define GBM 128
#define GBN 128
#define GBK 16

__device__ __forceinline__ uint32_t f2tf32(float f) {
    uint32_t u;
    asm("cvt.rna.tf32.f32 %0, %1;" : "=r"(u) : "f"(f));
    return u;
}

__device__ __forceinline__ void mma_tf32(float c[4], const uint32_t a[4],
                                         const uint32_t b[2]) {
    asm volatile(
        "mma.sync.aligned.m16n8k8.row.col.f32.tf32.tf32.f32 "
        "{%0,%1,%2,%3}, {%4,%5,%6,%7}, {%8,%9}, {%0,%1,%2,%3};\n"
        : "+f"(c[0]), "+f"(c[1]), "+f"(c[2]), "+f"(c[3])
        : "r"(a[0]), "r"(a[1]), "r"(a[2]), "r"(a[3]), "r"(b[0]), "r"(b[1]));
}

__global__ __launch_bounds__(256)
void tf32_gemm_bias(const float* __restrict__ A, const float* __restrict__ B,
                    const float* __restrict__ bias, float* __restrict__ C,
                    int M, int N, int K)
{
    __shared__ uint32_t As[GBM][GBK + 4];   // pad to 20 words: conflict-free frag reads
    __shared__ uint32_t Bs[GBK][GBN + 8];   // pad to 136 words: conflict-free frag reads

    const int tid  = threadIdx.x;
    const int wid  = tid >> 5;
    const int lane = tid & 31;
    const int m0 = blockIdx.y * GBM;
    const int n0 = blockIdx.x * GBN;

    const int wm = (wid & 3) * 32;    // warp m offset within block
    const int wn = (wid >> 2) * 64;   // warp n offset within block
    const int g  = lane >> 2;         // group 0..7
    const int tg = lane & 3;          // thread-in-group 0..3

    float c[2][8][4];
#pragma unroll
    for (int mt = 0; mt < 2; ++mt)
#pragma unroll
        for (int nt = 0; nt < 8; ++nt)
#pragma unroll
            for (int i = 0; i < 4; ++i) c[mt][nt][i] = 0.f;

    // staging register buffers for prefetch pipelining
    float4 avr[2], bvr[2];

    // A staging: s = tid + i*256 ; row = s>>2 ; c4 = s&3
    // B staging: s = tid + i*256 ; row = s>>5 ; c4 = s&31
    auto loadA = [&](int kc) {
#pragma unroll
        for (int i = 0; i < 2; ++i) {
            int s = tid + i * 256;
            avr[i] = *(const float4*)&A[(size_t)(m0 + (s >> 2)) * K + kc + (s & 3) * 4];
        }
    };
    auto loadB = [&](int kc) {
#pragma unroll
        for (int i = 0; i < 2; ++i) {
            int s = tid + i * 256;
            int col = n0 + (s & 31) * 4;
            if (col + 3 < N)
                bvr[i] = *(const float4*)&B[(size_t)(kc + (s >> 5)) * N + col];
            else
                bvr[i] = make_float4(0.f, 0.f, 0.f, 0.f);
        }
    };

    loadA(0);
    loadB(0);

    for (int kc = 0; kc < K; kc += GBK) {
        __syncthreads();   // prior compute done reading smem
        // stage to smem with tf32 rounding
#pragma unroll
        for (int i = 0; i < 2; ++i) {
            int s = tid + i * 256;
            uint32_t* p = &As[s >> 2][(s & 3) * 4];
            p[0] = f2tf32(avr[i].x); p[1] = f2tf32(avr[i].y);
            p[2] = f2tf32(avr[i].z); p[3] = f2tf32(avr[i].w);
        }
#pragma unroll
        for (int i = 0; i < 2; ++i) {
            int s = tid + i * 256;
            uint32_t* p = &Bs[s >> 5][(s & 31) * 4];
            p[0] = f2tf32(bvr[i].x); p[1] = f2tf32(bvr[i].y);
            p[2] = f2tf32(bvr[i].z); p[3] = f2tf32(bvr[i].w);
        }
        __syncthreads();

        if (kc + GBK < K) {   // prefetch next chunk (overlaps with mma)
            loadA(kc + GBK);
            loadB(kc + GBK);
        }

#pragma unroll
        for (int k8 = 0; k8 < GBK; k8 += 8) {
            uint32_t af[2][4];
#pragma unroll
            for (int mt = 0; mt < 2; ++mt) {
                int ra = wm + mt * 16 + g;
                af[mt][0] = As[ra][k8 + tg];
                af[mt][1] = As[ra + 8][k8 + tg];
                af[mt][2] = As[ra][k8 + tg + 4];
                af[mt][3] = As[ra + 8][k8 + tg + 4];
            }
            uint32_t bf[8][2];
#pragma unroll
            for (int nt = 0; nt < 8; ++nt) {
                int cn = wn + nt * 8 + g;
                bf[nt][0] = Bs[k8 + tg][cn];
                bf[nt][1] = Bs[k8 + tg + 4][cn];
            }
#pragma unroll
            for (int mt = 0; mt < 2; ++mt)
#pragma unroll
                for (int nt = 0; nt < 8; ++nt)
                    mma_tf32(c[mt][nt], af[mt], bf[nt]);
        }
    }

    // epilogue: c0/c1 at (row, col..col+1), c2/c3 at (row+8, ...)
#pragma unroll
    for (int mt = 0; mt < 2; ++mt) {
        int row = m0 + wm + mt * 16 + g;
#pragma unroll
        for (int nt = 0; nt < 8; ++nt) {
            int col = n0 + wn + nt * 8 + tg * 2;
            if (col < N) {
                float2 bb = *(const float2*)&bias[col];
                float2 v0 = make_float2(c[mt][nt][0] + bb.x, c[mt][nt][1] + bb.y);
                float2 v1 = make_float2(c[mt][nt][2] + bb.x, c[mt][nt][3] + bb.y);
                *(float2*)&C[(size_t)row * N + col] = v0;
                *(float2*)&C[(size_t)(row + 8) * N + col] = v1;
            }
        }
    }
}

// ============================================================================
// Recurrence kernels: float4-vectorized, conflict-free smem, register
// prefetch pipelining to hide L2 latency at chunk boundaries.
// ============================================================================
#define KC 256
#define PADW 4

__device__ __forceinline__ float sigf(float x) {
    return 1.f / (1.f + __expf(-x));
}

// gru_zr: blocks 0..63 compute Z cols [blk*16,+16); blocks 64..127 compute
// R (and G = R * Hprev) for cols [(blk-64)*16,+16).
__global__ __launch_bounds__(256)
void gru_zr(const float* __restrict__ Hprev,
            const float* __restrict__ Xz_t, const float* __restrict__ Xr_t,
            const float* __restrict__ Whz, const float* __restrict__ Whr,
            float* __restrict__ Z, float* __restrict__ G)
{
    __shared__ float Hp[32][KC + PADW];
    __shared__ float Wt[16][KC + PADW];

    const int tid = threadIdx.x;
    const bool isR = blockIdx.x >= 64;
    const int c0 = (blockIdx.x & 63) * 16;
    const float* __restrict__ W = isR ? Whr : Whz;

    const int b  = tid >> 3;
    const int nn = tid & 7;

    float4 a0 = make_float4(0.f, 0.f, 0.f, 0.f);
    float4 a1 = make_float4(0.f, 0.f, 0.f, 0.f);

    float4 hv[8];
    float  wv[16];

    auto loadRegs = [&](int kc) {
#pragma unroll
        for (int i = 0; i < 8; ++i) {
            int s = tid + i * 256;
            hv[i] = *(const float4*)&Hprev[(s >> 6) * HH + kc + (s & 63) * 4];
        }
#pragma unroll
        for (int i = 0; i < 16; ++i) {
            int s = tid + i * 256;
            wv[i] = W[(size_t)(kc + (s >> 4)) * HH + c0 + (s & 15)];
        }
    };

    loadRegs(0);

    for (int kc = 0; kc < HH; kc += KC) {
        __syncthreads();
#pragma unroll
        for (int i = 0; i < 8; ++i) {
            int s = tid + i * 256;
            *(float4*)&Hp[s >> 6][(s & 63) * 4] = hv[i];
        }
#pragma unroll
        for (int i = 0; i < 16; ++i) {
            int s = tid + i * 256;
            Wt[s & 15][s >> 4] = wv[i];
        }
        __syncthreads();

        if (kc + KC < HH) loadRegs(kc + KC);

#pragma unroll 8
        for (int kk = 0; kk < KC; kk += 4) {
            float4 h  = *(const float4*)&Hp[b][kk];
            float4 w0 = *(const float4*)&Wt[nn][kk];
            float4 w1 = *(const float4*)&Wt[nn + 8][kk];
            a0.x += h.x * w0.x; a0.y += h.y * w0.y;
            a0.z += h.z * w0.z; a0.w += h.w * w0.w;
            a1.x += h.x * w1.x; a1.y += h.y * w1.y;
            a1.z += h.z * w1.z; a1.w += h.w * w1.w;
        }
    }

    float s0 = (a0.x + a0.y) + (a0.z + a0.w);
    float s1 = (a1.x + a1.y) + (a1.z + a1.w);
    const int i0 = b * HH + c0 + nn;
    const int i1 = i0 + 8;

    if (!isR) {
        Z[i0] = sigf(Xz_t[i0] + s0);
        Z[i1] = sigf(Xz_t[i1] + s1);
    } else {
        float r0 = sigf(Xr_t[i0] + s0);
        float r1 = sigf(Xr_t[i1] + s1);
        G[i0] = r0 * Hprev[i0];
        G[i1] = r1 * Hprev[i1];
    }
}

// gru_h: 128 blocks x 8 cols. Hnew = Z*Hprev + (1-Z)*tanh(Xh + G @ Whh)
__global__ __launch_bounds__(256)
void gru_h(const float* __restrict__ Hprev, const float* __restrict__ G,
           const float* __restrict__ Xh_t, const float* __restrict__ Whh,
           const float* __restrict__ Z, float* __restrict__ Hout)
{
    __shared__ float Gp[32][KC + PADW];
    __shared__ float Wt[8][KC + PADW];

    const int tid = threadIdx.x;
    const int c0 = blockIdx.x * 8;

    const int b  = tid >> 3;
    const int nn = tid & 7;

    float4 a0 = make_float4(0.f, 0.f, 0.f, 0.f);

    float4 gv[8];
    float  wv[8];

    auto loadRegs = [&](int kc) {
#pragma unroll
        for (int i = 0; i < 8; ++i) {
            int s = tid + i * 256;
            gv[i] = *(const float4*)&G[(s >> 6) * HH + kc + (s & 63) * 4];
        }
#pragma unroll
        for (int i = 0; i < 8; ++i) {
            int s = tid + i * 256;
            wv[i] = Whh[(size_t)(kc + (s >> 3)) * HH + c0 + (s & 7)];
        }
    };

    loadRegs(0);

    for (int kc = 0; kc < HH; kc += KC) {
        __syncthreads();
#pragma unroll
        for (int i = 0; i < 8; ++i) {
            int s = tid + i * 256;
            *(float4*)&Gp[s >> 6][(s & 63) * 4] = gv[i];
        }
#pragma unroll
        for (int i = 0; i < 8; ++i) {
            int s = tid + i * 256;
            Wt[s & 7][s >> 3] = wv[i];
        }
        __syncthreads();

        if (kc + KC < HH) loadRegs(kc + KC);

#pragma unroll 8
        for (int kk = 0; kk < KC; kk += 4) {
            float4 g4 = *(const float4*)&Gp[b][kk];
            float4 w  = *(const float4*)&Wt[nn][kk];
            a0.x += g4.x * w.x; a0.y += g4.y * w.y;
            a0.z += g4.z * w.z; a0.w += g4.w * w.w;
        }
    }

    float s0 = (a0.x + a0.y) + (a0.z + a0.w);
    const int i0 = b * HH + c0 + nn;
    float ht = tanhf(Xh_t[i0] + s0);
    float z = Z[i0];
    Hout[i0] = z * Hprev[i0] + (1.f - z) * ht;
}

// ---------------- H_last copy ----------------------------------------------
__global__ void copy_hlast(const float* __restrict__ src, float* __restrict__ dst)
{
    int i = blockIdx.x * blockDim.x + threadIdx.x;
    if (i < BH) dst[i] = src[i];
}

// ---------------- launch ----------------------------------------------------
extern "C" void kernel_launch(void* const* d_in, const int* in_sizes, int n_in,
                              void* d_out, int out_size)
{
    const float* inputs = (const float*)d_in[0];
    const float* H0     = (const float*)d_in[1];
    const float* W_xz   = (const float*)d_in[2];
    const float* W_hz   = (const float*)d_in[3];
    const float* b_z    = (const float*)d_in[4];
    const float* W_xr   = (const float*)d_in[5];
    const float* W_hr   = (const float*)d_in[6];
    const float* b_r    = (const float*)d_in[7];
    const float* W_xh   = (const float*)d_in[8];
    const float* W_hh   = (const float*)d_in[9];
    const float* b_h    = (const float*)d_in[10];
    const float* W_hq   = (const float*)d_in[11];
    const float* b_q    = (const float*)d_in[12];

    float* out = (float*)d_out;

    float *Xz, *Xr, *Xh, *Hs, *Zb, *Gb;
    cudaGetSymbolAddress((void**)&Xz, g_Xz);
    cudaGetSymbolAddress((void**)&Xr, g_Xr);
    cudaGetSymbolAddress((void**)&Xh, g_Xh);
    cudaGetSymbolAddress((void**)&Hs, g_Hs);
    cudaGetSymbolAddress((void**)&Zb, g_Z);
    cudaGetSymbolAddress((void**)&Gb, g_G);

    // 1) input projections (TF32 tensor cores): [4096,10000]@[10000,1024]+bias
    {
        dim3 grid(HH / GBN, M1 / GBM);
        tf32_gemm_bias<<<grid, 256>>>(inputs, W_xz, b_z, Xz, M1, HH, VV);
        tf32_gemm_bias<<<grid, 256>>>(inputs, W_xr, b_r, Xr, M1, HH, VV);
        tf32_gemm_bias<<<grid, 256>>>(inputs, W_xh, b_h, Xh, M1, HH, VV);
    }

    // 2) recurrence: 128 steps, 2 kernels each (fp32 for accuracy)
    for (int t = 0; t < TT; ++t) {
        const float* Hprev = (t == 0) ? H0 : (Hs + (size_t)(t - 1) * BH);
        const float* Xz_t = Xz + (size_t)t * BH;
        const float* Xr_t = Xr + (size_t)t * BH;
        const float* Xh_t = Xh + (size_t)t * BH;
        gru_zr<<<128, 256>>>(Hprev, Xz_t, Xr_t, W_hz, W_hr, Zb, Gb);
        gru_h<<<128, 256>>>(Hprev, Gb, Xh_t, W_hh, Zb, Hs + (size_t)t * BH);
    }

    // 3) output projection (TF32): [4096,1024]@[1024,10000]+b_q -> d_out
    {
        dim3 grid((VV + GBN - 1) / GBN, M1 / GBM);
        tf32_gemm_bias<<<grid, 256>>>(Hs, W_hq, b_q, out, M1, VV, HH);
    }

    // 4) H_last appended after outputs if the output buffer includes it
    if (out_size >= M1 * VV + BH) {
        copy_hlast<<<BH / 256, 256>>>(Hs + (size_t)(TT - 1) * BH,
                                      out + (size_t)M1 * VV);
    }
}

// round 5
// speedup vs baseline: 2.1843x; 1.0130x over previous
#include <cuda_runtime.h>
#include <cuda_bf16.h>
#include <math.h>
#include <stdint.h>

// Problem constants
#define TT 128
#define BB 32
#define VV 10000
#define HH 1024
#define M1 (TT*BB)          // 4096
#define BH (BB*HH)          // 32768

// ---------------- scratch (device globals; no allocation allowed) ----------
__device__ float g_Xz[M1*HH];
__device__ float g_Xr[M1*HH];
__device__ float g_Xh[M1*HH];
__device__ float g_Hs[TT*BB*HH];
__device__ float g_Z[BH];
__device__ float g_G[BH];
__device__ float g_WzT[HH*HH];
__device__ float g_WrT[HH*HH];
__device__ float g_WhT[HH*HH];

// ---------------- cp.async helpers -----------------------------------------
__device__ __forceinline__ uint32_t smem_u32(const void* p) {
    return (uint32_t)__cvta_generic_to_shared(p);
}
#define CP_ASYNC16(dst, src) \
    asm volatile("cp.async.cg.shared.global [%0], [%1], 16;\n" :: "r"(dst), "l"(src))
#define CP_COMMIT() asm volatile("cp.async.commit_group;\n" ::: "memory")
#define CP_WAIT(n)  asm volatile("cp.async.wait_group %0;\n" :: "n"(n) : "memory")

// ============================================================================
// TF32 tensor-core GEMM: C = A(MxK) * B(KxN) + bias   (unchanged from R3)
// ============================================================================
#define GBM 128
#define GBN 128
#define GBK 16

__device__ __forceinline__ uint32_t f2tf32(float f) {
    uint32_t u;
    asm("cvt.rna.tf32.f32 %0, %1;" : "=r"(u) : "f"(f));
    return u;
}

__device__ __forceinline__ void mma_tf32(float c[4], const uint32_t a[4],
                                         const uint32_t b[2]) {
    asm volatile(
        "mma.sync.aligned.m16n8k8.row.col.f32.tf32.tf32.f32 "
        "{%0,%1,%2,%3}, {%4,%5,%6,%7}, {%8,%9}, {%0,%1,%2,%3};\n"
        : "+f"(c[0]), "+f"(c[1]), "+f"(c[2]), "+f"(c[3])
        : "r"(a[0]), "r"(a[1]), "r"(a[2]), "r"(a[3]), "r"(b[0]), "r"(b[1]));
}

__global__ __launch_bounds__(256)
void tf32_gemm_bias(const float* __restrict__ A, const float* __restrict__ B,
                    const float* __restrict__ bias, float* __restrict__ C,
                    int M, int N, int K)
{
    __shared__ uint32_t As[GBM][GBK + 4];
    __shared__ uint32_t Bs[GBK][GBN + 8];

    const int tid  = threadIdx.x;
    const int wid  = tid >> 5;
    const int lane = tid & 31;
    const int m0 = blockIdx.y * GBM;
    const int n0 = blockIdx.x * GBN;

    const int wm = (wid & 3) * 32;
    const int wn = (wid >> 2) * 64;
    const int g  = lane >> 2;
    const int tg = lane & 3;

    float c[2][8][4];
#pragma unroll
    for (int mt = 0; mt < 2; ++mt)
#pragma unroll
        for (int nt = 0; nt < 8; ++nt)
#pragma unroll
            for (int i = 0; i < 4; ++i) c[mt][nt][i] = 0.f;

    float4 avr[2], bvr[2];

    auto loadA = [&](int kc) {
#pragma unroll
        for (int i = 0; i < 2; ++i) {
            int s = tid + i * 256;
            avr[i] = *(const float4*)&A[(size_t)(m0 + (s >> 2)) * K + kc + (s & 3) * 4];
        }
    };
    auto loadB = [&](int kc) {
#pragma unroll
        for (int i = 0; i < 2; ++i) {
            int s = tid + i * 256;
            int col = n0 + (s & 31) * 4;
            if (col + 3 < N)
                bvr[i] = *(const float4*)&B[(size_t)(kc + (s >> 5)) * N + col];
            else
                bvr[i] = make_float4(0.f, 0.f, 0.f, 0.f);
        }
    };

    loadA(0);
    loadB(0);

    for (int kc = 0; kc < K; kc += GBK) {
        __syncthreads();
#pragma unroll
        for (int i = 0; i < 2; ++i) {
            int s = tid + i * 256;
            uint32_t* p = &As[s >> 2][(s & 3) * 4];
            p[0] = f2tf32(avr[i].x); p[1] = f2tf32(avr[i].y);
            p[2] = f2tf32(avr[i].z); p[3] = f2tf32(avr[i].w);
        }
#pragma unroll
        for (int i = 0; i < 2; ++i) {
            int s = tid + i * 256;
            uint32_t* p = &Bs[s >> 5][(s & 31) * 4];
            p[0] = f2tf32(bvr[i].x); p[1] = f2tf32(bvr[i].y);
            p[2] = f2tf32(bvr[i].z); p[3] = f2tf32(bvr[i].w);
        }
        __syncthreads();

        if (kc + GBK < K) {
            loadA(kc + GBK);
            loadB(kc + GBK);
        }

#pragma unroll
        for (int k8 = 0; k8 < GBK; k8 += 8) {
            uint32_t af[2][4];
#pragma unroll
            for (int mt = 0; mt < 2; ++mt) {
                int ra = wm + mt * 16 + g;
                af[mt][0] = As[ra][k8 + tg];
                af[mt][1] = As[ra + 8][k8 + tg];
                af[mt][2] = As[ra][k8 + tg + 4];
                af[mt][3] = As[ra + 8][k8 + tg + 4];
            }
            uint32_t bf[8][2];
#pragma unroll
            for (int nt = 0; nt < 8; ++nt) {
                int cn = wn + nt * 8 + g;
                bf[nt][0] = Bs[k8 + tg][cn];
                bf[nt][1] = Bs[k8 + tg + 4][cn];
            }
#pragma unroll
            for (int mt = 0; mt < 2; ++mt)
#pragma unroll
                for (int nt = 0; nt < 8; ++nt)
                    mma_tf32(c[mt][nt], af[mt], bf[nt]);
        }
    }

#pragma unroll
    for (int mt = 0; mt < 2; ++mt) {
        int row = m0 + wm + mt * 16 + g;
#pragma unroll
        for (int nt = 0; nt < 8; ++nt) {
            int col = n0 + wn + nt * 8 + tg * 2;
            if (col < N) {
                float2 bb = *(const float2*)&bias[col];
                float2 v0 = make_float2(c[mt][nt][0] + bb.x, c[mt][nt][1] + bb.y);
                float2 v1 = make_float2(c[mt][nt][2] + bb.x, c[mt][nt][3] + bb.y);
                *(float2*)&C[(size_t)row * N + col] = v0;
                *(float2*)&C[(size_t)(row + 8) * N + col] = v1;
            }
        }
    }
}

// ============================================================================
// 1024x1024 transpose (tiled, conflict-free): out[c][k] = in[k][c]
// ============================================================================
__global__ __launch_bounds__(256)
void transpose1024(const float* __restrict__ in, float* __restrict__ out)
{
    __shared__ float t[32][33];
    int x = blockIdx.x * 32 + threadIdx.x;
    int y0 = blockIdx.y * 32 + threadIdx.y;
#pragma unroll
    for (int j = 0; j < 32; j += 8)
        t[threadIdx.y + j][threadIdx.x] = in[(size_t)(y0 + j) * HH + x];
    __syncthreads();
    int xo = blockIdx.y * 32 + threadIdx.x;
    int yo = blockIdx.x * 32 + threadIdx.y;
#pragma unroll
    for (int j = 0; j < 32; j += 8)
        out[(size_t)(yo + j) * HH + xo] = t[threadIdx.x][threadIdx.y + j];
}

// ============================================================================
// Recurrence kernels v3: cp.async double-buffered smem, KC=128, transposed W.
// ============================================================================
#define KC2 128
#define PADW 4

__device__ __forceinline__ float sigf(float x) {
    return 1.f / (1.f + __expf(-x));
}

// gru_zr: blocks 0..63 -> Z cols [blk*16,+16); blocks 64..127 -> R/G cols.
__global__ __launch_bounds__(256)
void gru_zr(const float* __restrict__ Hprev,
            const float* __restrict__ Xz_t, const float* __restrict__ Xr_t,
            const float* __restrict__ WzT, const float* __restrict__ WrT,
            float* __restrict__ Z, float* __restrict__ G)
{
    __shared__ float Hp[2][32][KC2 + PADW];
    __shared__ float Wt[2][16][KC2 + PADW];

    const int tid = threadIdx.x;
    const bool isR = blockIdx.x >= 64;
    const int c0 = (blockIdx.x & 63) * 16;
    const float* __restrict__ WT = isR ? WrT : WzT;

    const int b  = tid >> 3;
    const int nn = tid & 7;

    float4 a0 = make_float4(0.f, 0.f, 0.f, 0.f);
    float4 a1 = make_float4(0.f, 0.f, 0.f, 0.f);

    auto load_chunk = [&](int buf, int kc) {
        // Hp: 32 x 128 floats = 1024 float4 -> 4 per thread (coalesced rows)
#pragma unroll
        for (int i = 0; i < 4; ++i) {
            int s = tid + i * 256;
            uint32_t d = smem_u32(&Hp[buf][s >> 5][(s & 31) * 4]);
            CP_ASYNC16(d, &Hprev[(s >> 5) * HH + kc + (s & 31) * 4]);
        }
        // Wt: 16 rows (cols of W) x 128 floats = 512 float4 -> 2 per thread
#pragma unroll
        for (int i = 0; i < 2; ++i) {
            int s = tid + i * 256;
            uint32_t d = smem_u32(&Wt[buf][s >> 5][(s & 31) * 4]);
            CP_ASYNC16(d, &WT[(size_t)(c0 + (s >> 5)) * HH + kc + (s & 31) * 4]);
        }
        CP_COMMIT();
    };

    load_chunk(0, 0);

#pragma unroll 1
    for (int c = 0; c < HH / KC2; ++c) {
        if (c + 1 < HH / KC2) {
            load_chunk((c + 1) & 1, (c + 1) * KC2);
            CP_WAIT(1);
        } else {
            CP_WAIT(0);
        }
        __syncthreads();

        const int buf = c & 1;
#pragma unroll
        for (int kk = 0; kk < KC2; kk += 4) {
            float4 h  = *(const float4*)&Hp[buf][b][kk];
            float4 w0 = *(const float4*)&Wt[buf][nn][kk];
            float4 w1 = *(const float4*)&Wt[buf][nn + 8][kk];
            a0.x += h.x * w0.x; a0.y += h.y * w0.y;
            a0.z += h.z * w0.z; a0.w += h.w * w0.w;
            a1.x += h.x * w1.x; a1.y += h.y * w1.y;
            a1.z += h.z * w1.z; a1.w += h.w * w1.w;
        }
        __syncthreads();
    }

    float s0 = (a0.x + a0.y) + (a0.z + a0.w);
    float s1 = (a1.x + a1.y) + (a1.z + a1.w);
    const int i0 = b * HH + c0 + nn;
    const int i1 = i0 + 8;

    if (!isR) {
        Z[i0] = sigf(Xz_t[i0] + s0);
        Z[i1] = sigf(Xz_t[i1] + s1);
    } else {
        float r0 = sigf(Xr_t[i0] + s0);
        float r1 = sigf(Xr_t[i1] + s1);
        G[i0] = r0 * Hprev[i0];
        G[i1] = r1 * Hprev[i1];
    }
}

// gru_h: 128 blocks x 8 cols. Hnew = Z*Hprev + (1-Z)*tanh(Xh + G @ Whh)
__global__ __launch_bounds__(256)
void gru_h(const float* __restrict__ Hprev, const float* __restrict__ G,
           const float* __restrict__ Xh_t, const float* __restrict__ WhT,
           const float* __restrict__ Z, float* __restrict__ Hout)
{
    __shared__ float Gp[2][32][KC2 + PADW];
    __shared__ float Wt[2][8][KC2 + PADW];

    const int tid = threadIdx.x;
    const int c0 = blockIdx.x * 8;

    const int b  = tid >> 3;
    const int nn = tid & 7;

    float4 a0 = make_float4(0.f, 0.f, 0.f, 0.f);

    auto load_chunk = [&](int buf, int kc) {
#pragma unroll
        for (int i = 0; i < 4; ++i) {
            int s = tid + i * 256;
            uint32_t d = smem_u32(&Gp[buf][s >> 5][(s & 31) * 4]);
            CP_ASYNC16(d, &G[(s >> 5) * HH + kc + (s & 31) * 4]);
        }
        // Wt: 8 rows x 128 floats = 256 float4 -> 1 per thread
        {
            int s = tid;
            uint32_t d = smem_u32(&Wt[buf][s >> 5][(s & 31) * 4]);
            CP_ASYNC16(d, &WhT[(size_t)(c0 + (s >> 5)) * HH + kc + (s & 31) * 4]);
        }
        CP_COMMIT();
    };

    load_chunk(0, 0);

#pragma unroll 1
    for (int c = 0; c < HH / KC2; ++c) {
        if (c + 1 < HH / KC2) {
            load_chunk((c + 1) & 1, (c + 1) * KC2);
            CP_WAIT(1);
        } else {
            CP_WAIT(0);
        }
        __syncthreads();

        const int buf = c & 1;
#pragma unroll
        for (int kk = 0; kk < KC2; kk += 4) {
            float4 g4 = *(const float4*)&Gp[buf][b][kk];
            float4 w  = *(const float4*)&Wt[buf][nn][kk];
            a0.x += g4.x * w.x; a0.y += g4.y * w.y;
            a0.z += g4.z * w.z; a0.w += g4.w * w.w;
        }
        __syncthreads();
    }

    float s0 = (a0.x + a0.y) + (a0.z + a0.w);
    const int i0 = b * HH + c0 + nn;
    float ht = tanhf(Xh_t[i0] + s0);
    float z = Z[i0];
    Hout[i0] = z * Hprev[i0] + (1.f - z) * ht;
}

// ---------------- H_last copy ----------------------------------------------
__global__ void copy_hlast(const float* __restrict__ src, float* __restrict__ dst)
{
    int i = blockIdx.x * blockDim.x + threadIdx.x;
    if (i < BH) dst[i] = src[i];
}

// ---------------- launch ----------------------------------------------------
extern "C" void kernel_launch(void* const* d_in, const int* in_sizes, int n_in,
                              void* d_out, int out_size)
{
    const float* inputs = (const float*)d_in[0];
    const float* H0     = (const float*)d_in[1];
    const float* W_xz   = (const float*)d_in[2];
    const float* W_hz   = (const float*)d_in[3];
    const float* b_z    = (const float*)d_in[4];
    const float* W_xr   = (const float*)d_in[5];
    const float* W_hr   = (const float*)d_in[6];
    const float* b_r    = (const float*)d_in[7];
    const float* W_xh   = (const float*)d_in[8];
    const float* W_hh   = (const float*)d_in[9];
    const float* b_h    = (const float*)d_in[10];
    const float* W_hq   = (const float*)d_in[11];
    const float* b_q    = (const float*)d_in[12];

    float* out = (float*)d_out;

    float *Xz, *Xr, *Xh, *Hs, *Zb, *Gb, *WzT, *WrT, *WhT;
    cudaGetSymbolAddress((void**)&Xz, g_Xz);
    cudaGetSymbolAddress((void**)&Xr, g_Xr);
    cudaGetSymbolAddress((void**)&Xh, g_Xh);
    cudaGetSymbolAddress((void**)&Hs, g_Hs);
    cudaGetSymbolAddress((void**)&Zb, g_Z);
    cudaGetSymbolAddress((void**)&Gb, g_G);
    cudaGetSymbolAddress((void**)&WzT, g_WzT);
    cudaGetSymbolAddress((void**)&WrT, g_WrT);
    cudaGetSymbolAddress((void**)&WhT, g_WhT);

    // 0) transpose recurrent weights (once per call, ~10us)
    {
        dim3 tg(32, 32), tb(32, 8);
        transpose1024<<<tg, tb>>>(W_hz, WzT);
        transpose1024<<<tg, tb>>>(W_hr, WrT);
        transpose1024<<<tg, tb>>>(W_hh, WhT);
    }

    // 1) input projections (TF32 tensor cores)
    {
        dim3 grid(HH / GBN, M1 / GBM);
        tf32_gemm_bias<<<grid, 256>>>(inputs, W_xz, b_z, Xz, M1, HH, VV);
        tf32_gemm_bias<<<grid, 256>>>(inputs, W_xr, b_r, Xr, M1, HH, VV);
        tf32_gemm_bias<<<grid, 256>>>(inputs, W_xh, b_h, Xh, M1, HH, VV);
    }

    // 2) recurrence: 128 steps, 2 kernels each (fp32 for accuracy)
    for (int t = 0; t < TT; ++t) {
        const float* Hprev = (t == 0) ? H0 : (Hs + (size_t)(t - 1) * BH);
        const float* Xz_t = Xz + (size_t)t * BH;
        const float* Xr_t = Xr + (size_t)t * BH;
        const float* Xh_t = Xh + (size_t)t * BH;
        gru_zr<<<128, 256>>>(Hprev, Xz_t, Xr_t, WzT, WrT, Zb, Gb);
        gru_h<<<128, 256>>>(Hprev, Gb, Xh_t, WhT, Zb, Hs + (size_t)t * BH);
    }

    // 3) output projection (TF32)
    {
        dim3 grid((VV + GBN - 1) / GBN, M1 / GBM);
        tf32_gemm_bias<<<grid, 256>>>(Hs, W_hq, b_q, out, M1, VV, HH);
    }

    // 4) H_last appended after outputs if the output buffer includes it
    if (out_size >= M1 * VV + BH) {
        copy_hlast<<<BH / 256, 256>>>(Hs + (size_t)(TT - 1) * BH,
                                      out + (size_t)M1 * VV);
    }
}